// round 4
// baseline (speedup 1.0000x reference)
#include <cuda_runtime.h>

#define BATCH 32
#define DIM 96
#define HH 128
#define WW 128
#define CR 24            // DIM / 4
#define KK 9             // 3x3
#define PLANE_ELEMS (HH * WW)          // 16384
#define PLANE_F4 (PLANE_ELEMS / 4)     // 4096
#define NPLANES (BATCH * DIM)          // 3072
#define BN_EPS 1e-5f

#define GROUPS 2
#define SPG (BATCH / GROUPS)           // 16 samples per group
#define PPG (SPG * DIM)                // 1536 planes per group (100.7 MB -> fits L2)

// scratch (no allocations allowed)
__device__ float g_pooled[NPLANES];          // [b][c] mean
__device__ float g_wdyn[NPLANES * KK];       // [b][c][3][3]

// ---------------------------------------------------------------------------
// Kernel 1: global average pool, one block per plane (within a sample group).
// Reads are default-cached: they deliberately warm L2 for the dwconv pass.
// ---------------------------------------------------------------------------
__global__ void pool_kernel(const float* __restrict__ x, int base_plane) {
    const int plane = base_plane + blockIdx.x;
    const float4* __restrict__ x4 = (const float4*)(x) + (size_t)plane * PLANE_F4;
    const int tid = threadIdx.x;

    float acc = 0.f;
#pragma unroll 4
    for (int i = tid; i < PLANE_F4; i += 256) {
        float4 v = x4[i];
        acc += (v.x + v.y) + (v.z + v.w);
    }
#pragma unroll
    for (int off = 16; off > 0; off >>= 1)
        acc += __shfl_xor_sync(0xffffffffu, acc, off);

    __shared__ float warp_sums[8];
    if ((tid & 31) == 0) warp_sums[tid >> 5] = acc;
    __syncthreads();
    if (tid == 0) {
        float s = 0.f;
#pragma unroll
        for (int w = 0; w < 8; w++) s += warp_sums[w];
        g_pooled[plane] = s * (1.0f / (float)PLANE_ELEMS);
    }
}

// ---------------------------------------------------------------------------
// Kernel 2: dynamic weight generation. One block per batch sample in group.
// ---------------------------------------------------------------------------
__global__ void weight_kernel(const float* __restrict__ w1,      // [CR, DIM]
                              const float* __restrict__ gamma,
                              const float* __restrict__ beta,
                              const float* __restrict__ rmean,
                              const float* __restrict__ rvar,
                              const float* __restrict__ w2,      // [DIM*KK, CR]
                              const float* __restrict__ b2,
                              int base_sample) {
    const int b = base_sample + blockIdx.x;
    const int tid = threadIdx.x;   // 128 threads

    __shared__ float pooled_s[DIM];
    __shared__ float h1_s[CR];

    if (tid < DIM) pooled_s[tid] = g_pooled[b * DIM + tid];
    __syncthreads();

    if (tid < CR) {
        float acc = 0.f;
        const float* wrow = w1 + tid * DIM;
#pragma unroll 8
        for (int i = 0; i < DIM; i++) acc += pooled_s[i] * wrow[i];
        float z = (acc - rmean[tid]) * rsqrtf(rvar[tid] + BN_EPS) * gamma[tid] + beta[tid];
        h1_s[tid] = 1.0f / (1.0f + __expf(-z));
    }
    __syncthreads();

    const int nout = DIM * KK;  // 864
    for (int o = tid; o < nout; o += 128) {
        const float* wrow = w2 + o * CR;
        float acc = b2[o];
#pragma unroll
        for (int i = 0; i < CR; i++) acc += h1_s[i] * wrow[i];
        g_wdyn[b * nout + o] = acc;
    }
}

// ---------------------------------------------------------------------------
// Kernel 3: per-sample depthwise 3x3, stride 1, pad 1 — register-window,
// no smem. One WARP per (plane, 32-row chunk). Input reads come from L2
// (warmed by pool_kernel of the same group). Output stores use __stcs so the
// 100 MB of writes do not evict the group's x tile from L2.
// ---------------------------------------------------------------------------
#define CHUNKS 4
#define CHUNK_H (HH / CHUNKS)   // 32

__global__ __launch_bounds__(128) void dwconv_kernel(const float* __restrict__ x,
                                                     const float* __restrict__ bias,
                                                     float* __restrict__ out,
                                                     int base_plane) {
    const int wid = threadIdx.x >> 5;
    const int tx  = threadIdx.x & 31;
    const int lin = blockIdx.x * 4 + wid;          // 0 .. PPG*CHUNKS-1
    const int plane = base_plane + (lin >> 2);
    const int chunk = lin & 3;
    const int c = plane % DIM;
    const int r0 = chunk * CHUNK_H;

    const float4* __restrict__ x4   = (const float4*)(x) + (size_t)plane * PLANE_F4;
    float4*       __restrict__ out4 = (float4*)(out)     + (size_t)plane * PLANE_F4;

    const float* wp = g_wdyn + plane * KK;         // uniform -> broadcast loads
    const float w00 = wp[0], w01 = wp[1], w02 = wp[2];
    const float w10 = wp[3], w11 = wp[4], w12 = wp[5];
    const float w20 = wp[6], w21 = wp[7], w22 = wp[8];
    const float bv = bias[c];

    const float4 zero4 = make_float4(0.f, 0.f, 0.f, 0.f);

    // window rows: A = r-1, B = r, C = r+1 (r = current output row)
    float4 vA = (r0 == 0) ? zero4 : x4[(r0 - 1) * 32 + tx];
    float4 vB = x4[r0 * 32 + tx];
    float lA = __shfl_up_sync(0xffffffffu, vA.w, 1);
    float rA = __shfl_down_sync(0xffffffffu, vA.x, 1);
    float lB = __shfl_up_sync(0xffffffffu, vB.w, 1);
    float rB = __shfl_down_sync(0xffffffffu, vB.x, 1);
    if (tx == 0)  { lA = 0.f; lB = 0.f; }
    if (tx == 31) { rA = 0.f; rB = 0.f; }

#pragma unroll 4
    for (int i = 0; i < CHUNK_H; i++) {
        const int rn = r0 + i + 1;
        float4 vC = (rn < HH) ? x4[rn * 32 + tx] : zero4;
        float lC = __shfl_up_sync(0xffffffffu, vC.w, 1);
        float rC = __shfl_down_sync(0xffffffffu, vC.x, 1);
        if (tx == 0)  lC = 0.f;
        if (tx == 31) rC = 0.f;

        float4 o;
        o.x = bv + w00 * lA   + w01 * vA.x + w02 * vA.y
                 + w10 * lB   + w11 * vB.x + w12 * vB.y
                 + w20 * lC   + w21 * vC.x + w22 * vC.y;
        o.y = bv + w00 * vA.x + w01 * vA.y + w02 * vA.z
                 + w10 * vB.x + w11 * vB.y + w12 * vB.z
                 + w20 * vC.x + w21 * vC.y + w22 * vC.z;
        o.z = bv + w00 * vA.y + w01 * vA.z + w02 * vA.w
                 + w10 * vB.y + w11 * vB.z + w12 * vB.w
                 + w20 * vC.y + w21 * vC.z + w22 * vC.w;
        o.w = bv + w00 * vA.z + w01 * vA.w + w02 * rA
                 + w10 * vB.z + w11 * vB.w + w12 * rB
                 + w20 * vC.z + w21 * vC.w + w22 * rC;

        __stcs(&out4[(r0 + i) * 32 + tx], o);   // streaming store: keep L2 for x

        vA = vB; lA = lB; rA = rB;
        vB = vC; lB = lC; rB = rC;
    }
}

// ---------------------------------------------------------------------------
extern "C" void kernel_launch(void* const* d_in, const int* in_sizes, int n_in,
                              void* d_out, int out_size) {
    const float* x     = (const float*)d_in[0];
    const float* w1    = (const float*)d_in[1];
    const float* gamma = (const float*)d_in[2];
    const float* beta  = (const float*)d_in[3];
    const float* rmean = (const float*)d_in[4];
    const float* rvar  = (const float*)d_in[5];
    const float* w2    = (const float*)d_in[6];
    const float* b2    = (const float*)d_in[7];
    const float* bias  = (const float*)d_in[8];
    float* out = (float*)d_out;

    for (int g = 0; g < GROUPS; g++) {
        const int base_sample = g * SPG;
        const int base_plane  = base_sample * DIM;
        pool_kernel<<<PPG, 256>>>(x, base_plane);
        weight_kernel<<<SPG, 128>>>(w1, gamma, beta, rmean, rvar, w2, b2, base_sample);
        dwconv_kernel<<<PPG, 128>>>(x, bias, out, base_plane);
    }
}

// round 5
// speedup vs baseline: 1.1622x; 1.1622x over previous
#include <cuda_runtime.h>

#define BATCH 32
#define DIM 96
#define HH 128
#define WW 128
#define CR 24            // DIM / 4
#define KK 9             // 3x3
#define PLANE_ELEMS (HH * WW)          // 16384
#define PLANE_F4 (PLANE_ELEMS / 4)     // 4096
#define NPLANES (BATCH * DIM)          // 3072
#define BN_EPS 1e-5f

// task schedule: per sample, 96 pool tasks (1 plane each) and 48 conv tasks
// (2 planes each). conv(b) is ticketed 2 samples behind pool(b+2).
#define P_TASKS 96
#define C_TASKS 48
#define LAG 2
#define GROUP_SZ (P_TASKS + C_TASKS)               // 144
#define TOTAL_TICKETS (BATCH * GROUP_SZ)           // 4608

// scratch (no allocations allowed)
__device__ float g_pooled[NPLANES];
__device__ int   g_cnt[BATCH];
__device__ int   g_ticket;

// ---------------------------------------------------------------------------
__global__ void init_kernel() {
    const int tid = threadIdx.x;
    if (tid < BATCH) g_cnt[tid] = 0;
    if (tid == BATCH) g_ticket = 0;
}

// ---------------------------------------------------------------------------
__device__ __forceinline__ void do_pool(const float* __restrict__ x,
                                        int sample, int ch, int tid) {
    const int plane = sample * DIM + ch;
    const float4* __restrict__ x4 = (const float4*)(x) + (size_t)plane * PLANE_F4;

    float acc = 0.f;
#pragma unroll 4
    for (int i = tid; i < PLANE_F4; i += 256) {
        float4 v = x4[i];
        acc += (v.x + v.y) + (v.z + v.w);
    }
#pragma unroll
    for (int off = 16; off > 0; off >>= 1)
        acc += __shfl_xor_sync(0xffffffffu, acc, off);

    __shared__ float warp_sums[8];
    if ((tid & 31) == 0) warp_sums[tid >> 5] = acc;
    __syncthreads();
    if (tid == 0) {
        float s = 0.f;
#pragma unroll
        for (int w = 0; w < 8; w++) s += warp_sums[w];
        g_pooled[plane] = s * (1.0f / (float)PLANE_ELEMS);
        __threadfence();                       // publish before counting
        atomicAdd(&g_cnt[sample], 1);
    }
    __syncthreads();
}

// ---------------------------------------------------------------------------
__device__ __forceinline__ void do_conv(const float* __restrict__ x,
                                        const float* __restrict__ w1,
                                        const float* __restrict__ gamma,
                                        const float* __restrict__ beta,
                                        const float* __restrict__ rmean,
                                        const float* __restrict__ rvar,
                                        const float* __restrict__ w2,
                                        const float* __restrict__ b2,
                                        const float* __restrict__ bias,
                                        float* __restrict__ out,
                                        int sample, int idx, int tid) {
    __shared__ float pooled_s[DIM];
    __shared__ float h1_s[CR];
    __shared__ float wsh[2][KK];
    __shared__ float bsh[2];

    // wait for this sample's pool to complete
    if (tid == 0) {
        volatile int* c = &g_cnt[sample];
        while (*c < P_TASKS) __nanosleep(100);
    }
    __syncthreads();   // acquire for the block

    if (tid < DIM) pooled_s[tid] = g_pooled[sample * DIM + tid];
    __syncthreads();

    if (tid < CR) {
        float acc = 0.f;
        const float* wrow = w1 + tid * DIM;
#pragma unroll 8
        for (int i = 0; i < DIM; i++) acc += pooled_s[i] * wrow[i];
        float z = (acc - rmean[tid]) * rsqrtf(rvar[tid] + BN_EPS) * gamma[tid] + beta[tid];
        h1_s[tid] = 1.0f / (1.0f + __expf(-z));
    }
    __syncthreads();

    const int c0 = idx * 2;                       // first of 2 channels
    if (tid < 2 * KK) {
        const int pl = tid / KK, o = tid % KK;
        const int row = (c0 + pl) * KK + o;
        const float* wrow = w2 + row * CR;
        float acc = b2[row];
#pragma unroll
        for (int i = 0; i < CR; i++) acc += h1_s[i] * wrow[i];
        wsh[pl][o] = acc;
    }
    if (tid < 2) bsh[tid] = bias[c0 + tid];
    __syncthreads();

    // 8 warps: warp w -> plane c0 + (w>>2), 32-row chunk (w&3)
    const int w  = tid >> 5;
    const int tx = tid & 31;
    const int pl = w >> 2;
    const int r0 = (w & 3) * 32;
    const int plane = sample * DIM + c0 + pl;

    const float4* __restrict__ x4   = (const float4*)(x) + (size_t)plane * PLANE_F4;
    float4*       __restrict__ out4 = (float4*)(out)     + (size_t)plane * PLANE_F4;

    const float w00 = wsh[pl][0], w01 = wsh[pl][1], w02 = wsh[pl][2];
    const float w10 = wsh[pl][3], w11 = wsh[pl][4], w12 = wsh[pl][5];
    const float w20 = wsh[pl][6], w21 = wsh[pl][7], w22 = wsh[pl][8];
    const float bv = bsh[pl];

    const float4 zero4 = make_float4(0.f, 0.f, 0.f, 0.f);

    float4 vA = (r0 == 0) ? zero4 : x4[(r0 - 1) * 32 + tx];
    float4 vB = x4[r0 * 32 + tx];
    float lA = __shfl_up_sync(0xffffffffu, vA.w, 1);
    float rA = __shfl_down_sync(0xffffffffu, vA.x, 1);
    float lB = __shfl_up_sync(0xffffffffu, vB.w, 1);
    float rB = __shfl_down_sync(0xffffffffu, vB.x, 1);
    if (tx == 0)  { lA = 0.f; lB = 0.f; }
    if (tx == 31) { rA = 0.f; rB = 0.f; }

#pragma unroll 4
    for (int i = 0; i < 32; i++) {
        const int rn = r0 + i + 1;
        float4 vC = (rn < HH) ? x4[rn * 32 + tx] : zero4;
        float lC = __shfl_up_sync(0xffffffffu, vC.w, 1);
        float rC = __shfl_down_sync(0xffffffffu, vC.x, 1);
        if (tx == 0)  lC = 0.f;
        if (tx == 31) rC = 0.f;

        float4 o;
        o.x = bv + w00 * lA   + w01 * vA.x + w02 * vA.y
                 + w10 * lB   + w11 * vB.x + w12 * vB.y
                 + w20 * lC   + w21 * vC.x + w22 * vC.y;
        o.y = bv + w00 * vA.x + w01 * vA.y + w02 * vA.z
                 + w10 * vB.x + w11 * vB.y + w12 * vB.z
                 + w20 * vC.x + w21 * vC.y + w22 * vC.z;
        o.z = bv + w00 * vA.y + w01 * vA.z + w02 * vA.w
                 + w10 * vB.y + w11 * vB.z + w12 * vB.w
                 + w20 * vC.y + w21 * vC.z + w22 * vC.w;
        o.w = bv + w00 * vA.z + w01 * vA.w + w02 * rA
                 + w10 * vB.z + w11 * vB.w + w12 * rB
                 + w20 * vC.z + w21 * vC.w + w22 * rC;

        out4[(r0 + i) * 32 + tx] = o;

        vA = vB; lA = lB; rA = rB;
        vB = vC; lB = lC; rB = rC;
    }
    __syncthreads();
}

// ---------------------------------------------------------------------------
__global__ __launch_bounds__(256) void worker_kernel(const float* __restrict__ x,
                                                     const float* __restrict__ w1,
                                                     const float* __restrict__ gamma,
                                                     const float* __restrict__ beta,
                                                     const float* __restrict__ rmean,
                                                     const float* __restrict__ rvar,
                                                     const float* __restrict__ w2,
                                                     const float* __restrict__ b2,
                                                     const float* __restrict__ bias,
                                                     float* __restrict__ out) {
    __shared__ int s_task;
    const int tid = threadIdx.x;

    for (;;) {
        __syncthreads();
        if (tid == 0) s_task = atomicAdd(&g_ticket, 1);
        __syncthreads();
        const int t = s_task;
        if (t >= TOTAL_TICKETS) return;

        // decode ticket -> task
        int sample, idx;
        bool is_pool;
        if (t < LAG * P_TASKS) {
            is_pool = true; sample = t / P_TASKS; idx = t % P_TASKS;
        } else {
            const int u = t - LAG * P_TASKS;
            const int g = u / GROUP_SZ;
            if (g < BATCH - LAG) {
                const int r = u % GROUP_SZ;
                if (r < P_TASKS) { is_pool = true;  sample = LAG + g; idx = r; }
                else             { is_pool = false; sample = g;       idx = r - P_TASKS; }
            } else {
                const int v = u - (BATCH - LAG) * GROUP_SZ;
                is_pool = false; sample = (BATCH - LAG) + v / C_TASKS; idx = v % C_TASKS;
            }
        }

        if (is_pool) do_pool(x, sample, idx, tid);
        else do_conv(x, w1, gamma, beta, rmean, rvar, w2, b2, bias, out,
                     sample, idx, tid);
    }
}

// ---------------------------------------------------------------------------
extern "C" void kernel_launch(void* const* d_in, const int* in_sizes, int n_in,
                              void* d_out, int out_size) {
    const float* x     = (const float*)d_in[0];
    const float* w1    = (const float*)d_in[1];
    const float* gamma = (const float*)d_in[2];
    const float* beta  = (const float*)d_in[3];
    const float* rmean = (const float*)d_in[4];
    const float* rvar  = (const float*)d_in[5];
    const float* w2    = (const float*)d_in[6];
    const float* b2    = (const float*)d_in[7];
    const float* bias  = (const float*)d_in[8];
    float* out = (float*)d_out;

    init_kernel<<<1, 64>>>();
    worker_kernel<<<1024, 256>>>(x, w1, gamma, beta, rmean, rvar, w2, b2, bias, out);
}